// round 7
// baseline (speedup 1.0000x reference)
#include <cuda_runtime.h>
#include <math.h>
#include <stdint.h>

// Problem constants
#define S_LEN   2048
#define E_DIM   1024
#define INNER_D 2048
#define NH_N    4
#define DH_N    512
#define M_ROWS  4096   // B*S
#define BH_N    8      // B*NH
#define STAGES  3

// ---------------- scratch (device globals; no allocs allowed) ----------------
__device__ float g_xpk   [(size_t)M_ROWS * E_DIM];     // packed tf32 x
__device__ float g_xinner[(size_t)M_ROWS * 4096];
__device__ float g_xact  [(size_t)M_ROWS * INNER_D];
__device__ float g_q     [(size_t)BH_N * S_LEN * DH_N];  // packed tf32
__device__ float g_k     [(size_t)BH_N * S_LEN * DH_N];  // packed tf32
__device__ float g_v     [(size_t)BH_N * S_LEN * DH_N];  // plain
__device__ float g_vT    [(size_t)BH_N * S_LEN * DH_N];  // packed tf32
__device__ float g_C     [(size_t)BH_N * S_LEN * S_LEN]; // packed tf32
__device__ float g_h     [(size_t)BH_N * S_LEN * DH_N];  // plain
__device__ float g_hstate[(size_t)M_ROWS * INNER_D];     // packed tf32
__device__ float g_WupT  [(size_t)4096 * 1024];          // packed tf32
__device__ float g_WdownT[(size_t)1024 * 2048];          // packed tf32
__device__ float g_ig    [BH_N * S_LEN];
__device__ float g_fgp   [BH_N * S_LEN];
__device__ float g_a     [BH_N * S_LEN];
__device__ float g_amax  [BH_N * S_LEN];
__device__ float g_enm   [BH_N * S_LEN];
__device__ float g_inorm [BH_N * S_LEN];
__device__ float g_rowsum[BH_N * S_LEN];

// ---------------- helpers ----------------
__device__ __forceinline__ uint32_t f2tf(float x) {
    uint32_t r;
    asm("cvt.rna.tf32.f32 %0, %1;" : "=r"(r) : "f"(x));
    return r;
}
__device__ __forceinline__ float f2tff(float x) { return __uint_as_float(f2tf(x)); }

// packed position of k within its 16-group
__device__ __forceinline__ int ppos(int k) {
    return (k & ~15) | ((k & 3) << 2) | ((k & 15) >> 2);
}

__device__ __forceinline__ void mma8(float* d, uint32_t a0, uint32_t a1,
                                     uint32_t a2, uint32_t a3,
                                     uint32_t b0, uint32_t b1) {
    asm volatile(
        "mma.sync.aligned.m16n8k8.row.col.f32.tf32.tf32.f32 "
        "{%0,%1,%2,%3},{%4,%5,%6,%7},{%8,%9},{%0,%1,%2,%3};"
        : "+f"(d[0]), "+f"(d[1]), "+f"(d[2]), "+f"(d[3])
        : "r"(a0), "r"(a1), "r"(a2), "r"(a3), "r"(b0), "r"(b1));
}
__device__ __forceinline__ void cp16(uint32_t dst, const float* src) {
    asm volatile("cp.async.cg.shared.global [%0], [%1], 16;" :: "r"(dst), "l"(src));
}
__device__ __forceinline__ void cp_commit() {
    asm volatile("cp.async.commit_group;" ::: "memory");
}
template<int N>
__device__ __forceinline__ void cp_wait() {
    asm volatile("cp.async.wait_group %0;" :: "n"(N) : "memory");
}

// ---------------- tf32 tensor-core GEMM: C[M,N] = A[M,K] @ B[N,K]^T ----------
// Operands pre-rounded tf32 + pre-packed. Block 128x128x32, 4 warps, warp
// tile 64x64 (2x2 warp grid), cp.async 3-stage pipeline, 2 blocks/SM.
// MODE 0: plain
// MODE 1: causal decay + fused row-sum; upper tiles skipped; y flipped; C packed
// MODE 2: per-row scale; K truncated to m0+128; y flipped (long blocks first)
template<int MODE>
__global__ __launch_bounds__(128, 2)
void gemm_tc(const float* __restrict__ A, const float* __restrict__ Bm,
             float* __restrict__ C, int Kd, int N,
             long long sA, long long sB, long long sC,
             const float* __restrict__ p1, const float* __restrict__ p2,
             float* __restrict__ rsum, float scale)
{
    const int my = (MODE != 0) ? (gridDim.y - 1 - blockIdx.y) : blockIdx.y;
    const int m0 = my * 128, n0 = blockIdx.x * 128;
    if (MODE == 1 && n0 > m0 + 127) return;   // never read by PV

    extern __shared__ float smem[];           // A: [STAGES][4096], B after
    const int bz = blockIdx.z;
    A  += (size_t)bz * sA;
    Bm += (size_t)bz * sB;
    C  += (size_t)bz * sC;
    const int tid = threadIdx.x, lane = tid & 31, warp = tid >> 5;
    const int wm = warp & 1, wn = warp >> 1;
    const int mbase = wm * 64, nbase = wn * 64;
    const int lr = lane >> 2, lc = lane & 3;
    const int zb = bz * S_LEN;
    const int Keff = (MODE == 2) ? (m0 + 128) : Kd;
    const int T = Keff >> 5;

    float acc[4][8][4];
#pragma unroll
    for (int i = 0; i < 4; i++)
#pragma unroll
        for (int j = 0; j < 8; j++)
#pragma unroll
            for (int r = 0; r < 4; r++) acc[i][j][r] = 0.f;

    // staging: thread t -> full row t of A and of B (8 quads over 2 chunks)
    const int sr = tid;
    const float* gA = A  + (size_t)(m0 + sr) * Kd;
    const float* gB = Bm + (size_t)(n0 + sr) * Kd;
    const uint32_t sbase = (uint32_t)__cvta_generic_to_shared(smem);
    uint32_t dA[8], dB[8];
#pragma unroll
    for (int i = 0; i < 8; i++) {
        int chunk = i >> 2, qq = i & 3;
        int sw = ((sr >> 1) ^ (chunk << 1)) & 3;
        uint32_t off = ((chunk * 128 + sr) * 16 + ((qq ^ sw) * 4)) * 4;
        dA[i] = sbase + off;
        dB[i] = sbase + STAGES * 16384 + off;
    }

    // prologue: stage 0 and 1
#pragma unroll
    for (int p = 0; p < 2; p++) {
        const float* pa = gA + p * 32;
        const float* pb = gB + p * 32;
        uint32_t so = p * 16384;
#pragma unroll
        for (int i = 0; i < 8; i++) {
            int src = (i >> 2) * 16 + (i & 3) * 4;
            cp16(dA[i] + so, pa + src);
            cp16(dB[i] + so, pb + src);
        }
        cp_commit();
    }

    for (int t = 0; t < T; t++) {
        if (t + 1 < T) cp_wait<1>(); else cp_wait<0>();
        __syncthreads();
        if (t + 2 < T) {
            const int stg = (t + 2) % STAGES;
            const float* pa = gA + (t + 2) * 32;
            const float* pb = gB + (t + 2) * 32;
            uint32_t so = stg * 16384;
#pragma unroll
            for (int i = 0; i < 8; i++) {
                int src = (i >> 2) * 16 + (i & 3) * 4;
                cp16(dA[i] + so, pa + src);
                cp16(dB[i] + so, pb + src);
            }
            cp_commit();
        }
        const int stg = t % STAGES;
#pragma unroll
        for (int ch = 0; ch < 2; ch++) {
            const float* ba = smem + stg * 4096 + ch * 2048;
            const float* bb = smem + STAGES * 4096 + stg * 4096 + ch * 2048;
            uint4 af[4][2]; uint4 bf[8];
#pragma unroll
            for (int mt = 0; mt < 4; mt++) {
                int row = mbase + mt * 16 + lr;
                int pq = lc ^ (((row >> 1) ^ (ch << 1)) & 3);
                af[mt][0] = *(const uint4*)(ba + row * 16 + pq * 4);
                af[mt][1] = *(const uint4*)(ba + (row + 8) * 16 + pq * 4);
            }
#pragma unroll
            for (int nt = 0; nt < 8; nt++) {
                int nr = nbase + nt * 8 + lr;
                int pq = lc ^ (((nr >> 1) ^ (ch << 1)) & 3);
                bf[nt] = *(const uint4*)(bb + nr * 16 + pq * 4);
            }
#pragma unroll
            for (int mt = 0; mt < 4; mt++)
#pragma unroll
                for (int nt = 0; nt < 8; nt++) {
                    mma8(acc[mt][nt], af[mt][0].x, af[mt][1].x, af[mt][0].y, af[mt][1].y,
                         bf[nt].x, bf[nt].y);
                    mma8(acc[mt][nt], af[mt][0].z, af[mt][1].z, af[mt][0].w, af[mt][1].w,
                         bf[nt].z, bf[nt].w);
                }
        }
    }

    // epilogue
    float ac0[8], ac1[8];
    if (MODE == 1) {
#pragma unroll
        for (int nt = 0; nt < 8; nt++) {
            int c = n0 + nbase + nt * 8 + lc * 2;
            ac0[nt] = p1[zb + c];
            ac1[nt] = p1[zb + c + 1];
        }
    }
#pragma unroll
    for (int mt = 0; mt < 4; mt++) {
        int r1 = m0 + mbase + mt * 16 + lr;
        int r2 = r1 + 8;
        float am1 = 0.f, am2 = 0.f, s1 = 1.f, s2 = 1.f;
        if (MODE == 1) { am1 = p2[zb + r1]; am2 = p2[zb + r2]; }
        if (MODE == 2) { s1 = p1[zb + r1]; s2 = p1[zb + r2]; }
        float rowacc1 = 0.f, rowacc2 = 0.f;
#pragma unroll
        for (int nt = 0; nt < 8; nt++) {
            int c = n0 + nbase + nt * 8 + lc * 2;
            float* a4 = acc[mt][nt];
            float o0 = a4[0], o1 = a4[1], o2 = a4[2], o3 = a4[3];
            if (MODE == 1) {
                o0 *= (c     <= r1) ? scale * __expf(fminf(ac0[nt] - am1, 0.f)) : 0.f;
                o1 *= (c + 1 <= r1) ? scale * __expf(fminf(ac1[nt] - am1, 0.f)) : 0.f;
                o2 *= (c     <= r2) ? scale * __expf(fminf(ac0[nt] - am2, 0.f)) : 0.f;
                o3 *= (c + 1 <= r2) ? scale * __expf(fminf(ac1[nt] - am2, 0.f)) : 0.f;
                rowacc1 += o0 + o1;
                rowacc2 += o2 + o3;
                int p0 = ppos(c);
                C[(size_t)r1 * N + p0]     = f2tff(o0);
                C[(size_t)r1 * N + p0 + 4] = f2tff(o1);
                C[(size_t)r2 * N + p0]     = f2tff(o2);
                C[(size_t)r2 * N + p0 + 4] = f2tff(o3);
            } else {
                if (MODE == 2) { o0 *= s1; o1 *= s1; o2 *= s2; o3 *= s2; }
                *(float2*)(C + (size_t)r1 * N + c) = make_float2(o0, o1);
                *(float2*)(C + (size_t)r2 * N + c) = make_float2(o2, o3);
            }
        }
        if (MODE == 1) {
            atomicAdd(rsum + zb + r1, rowacc1);
            atomicAdd(rsum + zb + r2, rowacc2);
        }
    }
}

// ---------------- pack x to tf32 quad-interleaved ----------------
__global__ void pack_x_k(const float* __restrict__ in, float* __restrict__ out)
{
    int g = blockIdx.x * 256 + threadIdx.x;
    const float* p = in + (size_t)g * 16;
    float4 va[4];
#pragma unroll
    for (int i = 0; i < 4; i++) va[i] = *(const float4*)(p + 4 * i);
    const float* vf = (const float*)va;
    float* o = out + (size_t)g * 16;
#pragma unroll
    for (int q = 0; q < 4; q++) {
        float4 w = make_float4(f2tff(vf[q]), f2tff(vf[q + 4]),
                               f2tff(vf[q + 8]), f2tff(vf[q + 12]));
        *(float4*)(o + q * 4) = w;
    }
}

// ---------------- transpose + tf32 round + pack ----------------
__global__ void transpose_pk_k(const float* __restrict__ in, float* __restrict__ out,
                               int R, int Cc, long long sIn, long long sOut)
{
    __shared__ float tile[32][33];
    in  += (size_t)blockIdx.z * sIn;
    out += (size_t)blockIdx.z * sOut;
    int c0 = blockIdx.x * 32, r0 = blockIdx.y * 32;
    int x = threadIdx.x, y = threadIdx.y;
#pragma unroll
    for (int j = 0; j < 32; j += 8)
        tile[y + j][x] = in[(size_t)(r0 + y + j) * Cc + c0 + x];
    __syncthreads();
    int px = (x & 16) | ((x & 3) << 2) | ((x & 15) >> 2);
#pragma unroll
    for (int j = 0; j < 32; j += 8)
        out[(size_t)(c0 + y + j) * R + r0 + px] = f2tff(tile[x][y + j]);
}

// ---------------- causal depthwise conv (K=4) + swish ----------------
__global__ void conv_swish_k(const float* __restrict__ xinner,
                             const float* __restrict__ cw,
                             const float* __restrict__ cb,
                             float* __restrict__ xact)
{
    int idx = blockIdx.x * 256 + threadIdx.x;
    int c = idx & 2047;
    int r = idx >> 11;
    int s = r & 2047;
    const float* base = xinner + (size_t)r * 4096 + c;
    float acc = cb[c];
#pragma unroll
    for (int i = 0; i < 4; i++) {
        int sp = s - 3 + i;
        if (sp >= 0) acc = fmaf(base[(long long)(i - 3) * 4096], cw[i * 2048 + c], acc);
    }
    xact[idx] = acc / (1.f + __expf(-acc));
}

// ---------------- headwise q/k/v + gate preactivations ----------------
__global__ void qkv_gates_k(const float* __restrict__ xinner, const float* __restrict__ xact,
    const float* __restrict__ Wq, const float* __restrict__ Wk, const float* __restrict__ Wv,
    const float* __restrict__ Wig, const float* __restrict__ big,
    const float* __restrict__ Wfg, const float* __restrict__ bfg,
    float* __restrict__ q, float* __restrict__ k, float* __restrict__ v,
    float* __restrict__ ig, float* __restrict__ fgp)
{
    int r = blockIdx.x;
    int b = r >> 11, s = r & 2047;
    int tid = threadIdx.x;
    float igp[4] = {0, 0, 0, 0}, fgv[4] = {0, 0, 0, 0};
#pragma unroll
    for (int g = 0; g < 2; g++) {
        int c4 = tid * 8 + g * 4;
        int ph = c4 >> 2;
        float xa[4], xm[4];
#pragma unroll
        for (int d = 0; d < 4; d++) {
            xa[d] = xact[(size_t)r * 2048 + c4 + d];
            xm[d] = xinner[(size_t)r * 4096 + c4 + d];
        }
#pragma unroll
        for (int o = 0; o < 4; o++) {
            float qo = 0, ko = 0, vo = 0;
#pragma unroll
            for (int d = 0; d < 4; d++) {
                qo = fmaf(xa[d], Wq[ph * 16 + o * 4 + d], qo);
                ko = fmaf(xa[d], Wk[ph * 16 + o * 4 + d], ko);
                vo = fmaf(xm[d], Wv[ph * 16 + o * 4 + d], vo);
            }
            int c = c4 + o;
            int nh = c >> 9, dh = c & 511;
            size_t rowb = ((size_t)(b * 4 + nh) * 2048 + s) * 512;
            int pp = ppos(dh);
            q[rowb + pp] = f2tff(qo);
            k[rowb + pp] = f2tff(ko);
            v[rowb + dh] = vo;
#pragma unroll
            for (int n2 = 0; n2 < 4; n2++) {
                igp[n2] = fmaf(qo, Wig[c * 4 + n2], igp[n2]);
                igp[n2] = fmaf(ko, Wig[(2048 + c) * 4 + n2], igp[n2]);
                igp[n2] = fmaf(vo, Wig[(4096 + c) * 4 + n2], igp[n2]);
                fgv[n2] = fmaf(qo, Wfg[c * 4 + n2], fgv[n2]);
                fgv[n2] = fmaf(ko, Wfg[(2048 + c) * 4 + n2], fgv[n2]);
                fgv[n2] = fmaf(vo, Wfg[(4096 + c) * 4 + n2], fgv[n2]);
            }
        }
    }
#pragma unroll
    for (int off = 16; off; off >>= 1) {
#pragma unroll
        for (int n2 = 0; n2 < 4; n2++) {
            igp[n2] += __shfl_down_sync(0xffffffffu, igp[n2], off);
            fgv[n2] += __shfl_down_sync(0xffffffffu, fgv[n2], off);
        }
    }
    __shared__ float red[8][8];
    int wid = tid >> 5, lane = tid & 31;
    if (lane == 0) {
#pragma unroll
        for (int n2 = 0; n2 < 4; n2++) { red[wid][n2] = igp[n2]; red[wid][4 + n2] = fgv[n2]; }
    }
    __syncthreads();
    if (tid < 8) {
        float acc = 0.f;
        for (int w = 0; w < 8; w++) acc += red[w][tid];
        int n2 = tid & 3;
        if (tid < 4) ig [(size_t)(b * 4 + n2) * 2048 + s] = acc + big[n2];
        else         fgp[(size_t)(b * 4 + n2) * 2048 + s] = acc + bfg[n2];
    }
}

// ---------------- per-head scans ----------------
__global__ void scan_k(const float* __restrict__ ig, const float* __restrict__ fgp,
                       float* __restrict__ ga, float* __restrict__ gamax,
                       float* __restrict__ genm)
{
    const int bh = blockIdx.x, tid = threadIdx.x;
    const int base = bh * 2048;
    const int lane = tid & 31, warp = tid >> 5;
    float lf[8], aL[8], F[8];
    float s = 0.f;
#pragma unroll
    for (int j = 0; j < 8; j++) {
        float xv = fgp[base + tid * 8 + j];
        lf[j] = fminf(xv, 0.f) - log1pf(expf(-fabsf(xv)));
        s += lf[j];
    }
    __shared__ float wred[8];
    float inc = s;
#pragma unroll
    for (int off = 1; off < 32; off <<= 1) {
        float o = __shfl_up_sync(0xffffffffu, inc, off);
        if (lane >= off) inc += o;
    }
    float exc = __shfl_up_sync(0xffffffffu, inc, 1);
    if (lane == 0) exc = 0.f;
    if (lane == 31) wred[warp] = inc;
    __syncthreads();
    float wofs = 0.f;
#pragma unroll
    for (int w = 0; w < 8; w++) if (w < warp) wofs += wred[w];
    float run = wofs + exc;
#pragma unroll
    for (int j = 0; j < 8; j++) { run += lf[j]; F[j] = run; }
    __syncthreads();

    float mloc = -3.4e38f;
#pragma unroll
    for (int j = 0; j < 8; j++) {
        aL[j] = ig[base + tid * 8 + j] - F[j];
        mloc = fmaxf(mloc, aL[j]);
    }
    float minc = mloc;
#pragma unroll
    for (int off = 1; off < 32; off <<= 1) {
        float o = __shfl_up_sync(0xffffffffu, minc, off);
        if (lane >= off) minc = fmaxf(minc, o);
    }
    float mexc = __shfl_up_sync(0xffffffffu, minc, 1);
    if (lane == 0) mexc = -3.4e38f;
    if (lane == 31) wred[warp] = minc;
    __syncthreads();
    float wm = -3.4e38f;
#pragma unroll
    for (int w = 0; w < 8; w++) if (w < warp) wm = fmaxf(wm, wred[w]);
    float rm = fmaxf(wm, mexc);
#pragma unroll
    for (int j = 0; j < 8; j++) {
        rm = fmaxf(rm, aL[j]);
        int idx = base + tid * 8 + j;
        ga[idx] = aL[j];
        gamax[idx] = rm;
        genm[idx] = expf(-(F[j] + rm));
    }
}

// ---------------- finalize: inorm = 1/(max(|rowsum|, enm) + 1e-6) -----------
__global__ void finalize_norm_k(const float* __restrict__ rs, const float* __restrict__ enm,
                                float* __restrict__ inorm)
{
    int i = blockIdx.x * 256 + threadIdx.x;
    float nrm = fmaxf(fabsf(rs[i]), enm[i]);
    inorm[i] = 1.f / (nrm + 1e-6f);
}

// ---------------- per-(b,s,nh) layernorm + skip + swish(z); packed store ----
__global__ void ln_fuse_k(const float* __restrict__ h, const float* __restrict__ xact,
    const float* __restrict__ xinner, const float* __restrict__ nw,
    const float* __restrict__ sk, float* __restrict__ hstate)
{
    int r = blockIdx.x, nh = blockIdx.y, tid = threadIdx.x;
    int b = r >> 11, s = r & 2047;
    const float* hp = h + ((size_t)(b * 4 + nh) * 2048 + s) * 512;
    float4 hv = *(const float4*)(hp + tid * 4);
    float sum = hv.x + hv.y + hv.z + hv.w;
    for (int off = 16; off; off >>= 1) sum += __shfl_down_sync(0xffffffffu, sum, off);
    __shared__ float sred[4];
    __shared__ float smu, srstd;
    int wid = tid >> 5, lane = tid & 31;
    if (lane == 0) sred[wid] = sum;
    __syncthreads();
    if (tid == 0) smu = (sred[0] + sred[1] + sred[2] + sred[3]) * (1.f / 512.f);
    __syncthreads();
    float mu = smu;
    float dx = hv.x - mu, dy = hv.y - mu, dz = hv.z - mu, dw = hv.w - mu;
    float sq = dx * dx + dy * dy + dz * dz + dw * dw;
    for (int off = 16; off; off >>= 1) sq += __shfl_down_sync(0xffffffffu, sq, off);
    __syncthreads();
    if (lane == 0) sred[wid] = sq;
    __syncthreads();
    if (tid == 0) srstd = rsqrtf((sred[0] + sred[1] + sred[2] + sred[3]) * (1.f / 512.f) + 1e-6f);
    __syncthreads();
    float rstd = srstd;
    int c0 = nh * 512 + tid * 4;
    float4 nwv = *(const float4*)(nw + c0);
    float4 skv = *(const float4*)(sk + c0);
    float4 xav = *(const float4*)(xact + (size_t)r * 2048 + c0);
    float4 zv  = *(const float4*)(xinner + (size_t)r * 4096 + 2048 + c0);
    float o[4];
    o[0] = (dx * rstd * nwv.x + skv.x * xav.x) * (zv.x / (1.f + __expf(-zv.x)));
    o[1] = (dy * rstd * nwv.y + skv.y * xav.y) * (zv.y / (1.f + __expf(-zv.y)));
    o[2] = (dz * rstd * nwv.z + skv.z * xav.z) * (zv.z / (1.f + __expf(-zv.z)));
    o[3] = (dw * rstd * nwv.w + skv.w * xav.w) * (zv.w / (1.f + __expf(-zv.w)));
    float* hb = hstate + (size_t)r * 2048 + (c0 & ~15) + (tid & 3);
#pragma unroll
    for (int i = 0; i < 4; i++) hb[i << 2] = f2tff(o[i]);
}

// ---------------- launch ----------------
extern "C" void kernel_launch(void* const* d_in, const int* in_sizes, int n_in,
                              void* d_out, int out_size)
{
    (void)in_sizes; (void)n_in; (void)out_size;
    const float* x      = (const float*)d_in[0];
    const float* W_up   = (const float*)d_in[1];
    const float* conv_w = (const float*)d_in[2];
    const float* conv_b = (const float*)d_in[3];
    const float* Wq     = (const float*)d_in[4];
    const float* Wk     = (const float*)d_in[5];
    const float* Wv     = (const float*)d_in[6];
    const float* W_ig   = (const float*)d_in[7];
    const float* b_ig   = (const float*)d_in[8];
    const float* W_fg   = (const float*)d_in[9];
    const float* b_fg   = (const float*)d_in[10];
    const float* norm_w = (const float*)d_in[11];
    const float* skipw  = (const float*)d_in[12];
    const float* W_down = (const float*)d_in[13];
    float* out = (float*)d_out;

    float *xpk, *xinner, *xact, *q, *k, *v, *vT, *Cb, *h, *hstate, *WupT, *WdownT;
    float *ig, *fgp, *a, *amax, *enm, *inorm, *rowsum;
    cudaGetSymbolAddress((void**)&xpk,    g_xpk);
    cudaGetSymbolAddress((void**)&xinner, g_xinner);
    cudaGetSymbolAddress((void**)&xact,   g_xact);
    cudaGetSymbolAddress((void**)&q,      g_q);
    cudaGetSymbolAddress((void**)&k,      g_k);
    cudaGetSymbolAddress((void**)&v,      g_v);
    cudaGetSymbolAddress((void**)&vT,     g_vT);
    cudaGetSymbolAddress((void**)&Cb,     g_C);
    cudaGetSymbolAddress((void**)&h,      g_h);
    cudaGetSymbolAddress((void**)&hstate, g_hstate);
    cudaGetSymbolAddress((void**)&WupT,   g_WupT);
    cudaGetSymbolAddress((void**)&WdownT, g_WdownT);
    cudaGetSymbolAddress((void**)&ig,     g_ig);
    cudaGetSymbolAddress((void**)&fgp,    g_fgp);
    cudaGetSymbolAddress((void**)&a,      g_a);
    cudaGetSymbolAddress((void**)&amax,   g_amax);
    cudaGetSymbolAddress((void**)&enm,    g_enm);
    cudaGetSymbolAddress((void**)&inorm,  g_inorm);
    cudaGetSymbolAddress((void**)&rowsum, g_rowsum);

    const int SMEM = STAGES * 2 * 16384;   // 96 KB
    cudaFuncSetAttribute((const void*)gemm_tc<0>, cudaFuncAttributeMaxDynamicSharedMemorySize, SMEM);
    cudaFuncSetAttribute((const void*)gemm_tc<1>, cudaFuncAttributeMaxDynamicSharedMemorySize, SMEM);
    cudaFuncSetAttribute((const void*)gemm_tc<2>, cudaFuncAttributeMaxDynamicSharedMemorySize, SMEM);

    const long long sQKV = (long long)S_LEN * DH_N;
    const long long sCC  = (long long)S_LEN * S_LEN;

    // 0) zero rowsum; pack x; transpose+round+pack weights
    cudaMemsetAsync(rowsum, 0, BH_N * S_LEN * sizeof(float));
    pack_x_k<<<(M_ROWS * E_DIM / 16) / 256, 256>>>(x, xpk);
    transpose_pk_k<<<dim3(128, 32, 1), dim3(32, 8)>>>(W_up,   WupT,   1024, 4096, 0, 0);
    transpose_pk_k<<<dim3(32,  64, 1), dim3(32, 8)>>>(W_down, WdownT, 2048, 1024, 0, 0);

    // 1) up projection
    gemm_tc<0><<<dim3(32, 32, 1), 128, SMEM>>>(xpk, WupT, xinner, 1024, 4096,
                                               0, 0, 0, nullptr, nullptr, nullptr, 0.f);
    // 2) causal conv + swish
    conv_swish_k<<<32768, 256>>>(xinner, conv_w, conv_b, xact);
    // 3) headwise q/k/v + gate preactivations
    qkv_gates_k<<<4096, 256>>>(xinner, xact, Wq, Wk, Wv, W_ig, b_ig, W_fg, b_fg,
                               q, k, v, ig, fgp);
    // 3b) transpose+round+pack V per head
    transpose_pk_k<<<dim3(16, 64, 8), dim3(32, 8)>>>(v, vT, 2048, 512, sQKV, sQKV);
    // 4) per-head scans
    scan_k<<<8, 256>>>(ig, fgp, a, amax, enm);
    // 5) weighted causal scores + fused row sums
    gemm_tc<1><<<dim3(16, 16, 8), 128, SMEM>>>(q, k, Cb, 512, 2048,
                                               sQKV, sQKV, sCC, a, amax, rowsum,
                                               0.044194173824159216f);
    // 6) finalize norms
    finalize_norm_k<<<64, 256>>>(rowsum, enm, inorm);
    // 7) h = diag(inorm) C @ V  (K truncated; longest blocks scheduled first)
    gemm_tc<2><<<dim3(4, 16, 8), 128, SMEM>>>(Cb, vT, h, 2048, 512,
                                              sCC, sQKV, sQKV, inorm, nullptr, nullptr, 0.f);
    // 8) multihead LN + skip + swish(z) gate
    ln_fuse_k<<<dim3(4096, 4), 128>>>(h, xact, xinner, norm_w, skipw, hstate);
    // 9) down projection -> output
    gemm_tc<0><<<dim3(8, 32, 1), 128, SMEM>>>(hstate, WdownT, out, 2048, 1024,
                                              0, 0, 0, nullptr, nullptr, nullptr, 0.f);
}

// round 8
// speedup vs baseline: 1.0113x; 1.0113x over previous
#include <cuda_runtime.h>
#include <math.h>
#include <stdint.h>

// Problem constants
#define S_LEN   2048
#define E_DIM   1024
#define INNER_D 2048
#define NH_N    4
#define DH_N    512
#define M_ROWS  4096   // B*S
#define BH_N    8      // B*NH
#define STAGES  3

// ---------------- scratch (device globals; no allocs allowed) ----------------
__device__ float g_xpk   [(size_t)M_ROWS * E_DIM];     // packed tf32 x
__device__ float g_xinner[(size_t)M_ROWS * 4096];
__device__ float g_xact  [(size_t)M_ROWS * INNER_D];
__device__ float g_q     [(size_t)BH_N * S_LEN * DH_N];  // packed tf32
__device__ float g_k     [(size_t)BH_N * S_LEN * DH_N];  // packed tf32
__device__ float g_v     [(size_t)BH_N * S_LEN * DH_N];  // plain
__device__ float g_vT    [(size_t)BH_N * S_LEN * DH_N];  // packed tf32
__device__ float g_C     [(size_t)BH_N * S_LEN * S_LEN]; // packed tf32 (upper tri stays 0)
__device__ float g_h     [(size_t)BH_N * S_LEN * DH_N];  // plain
__device__ float g_hstate[(size_t)M_ROWS * INNER_D];     // packed tf32
__device__ float g_WupT  [(size_t)4096 * 1024];          // packed tf32
__device__ float g_WdownT[(size_t)1024 * 2048];          // packed tf32
__device__ float g_ig    [BH_N * S_LEN];
__device__ float g_fgp   [BH_N * S_LEN];
__device__ float g_a     [BH_N * S_LEN];
__device__ float g_amax  [BH_N * S_LEN];
__device__ float g_enm   [BH_N * S_LEN];
__device__ float g_inorm [BH_N * S_LEN];
__device__ float g_rowsum[BH_N * S_LEN];

// ---------------- helpers ----------------
__device__ __forceinline__ uint32_t f2tf(float x) {
    uint32_t r;
    asm("cvt.rna.tf32.f32 %0, %1;" : "=r"(r) : "f"(x));
    return r;
}
__device__ __forceinline__ float f2tff(float x) { return __uint_as_float(f2tf(x)); }

// packed position of k within its 16-group
__device__ __forceinline__ int ppos(int k) {
    return (k & ~15) | ((k & 3) << 2) | ((k & 15) >> 2);
}

__device__ __forceinline__ void mma8(float* d, uint32_t a0, uint32_t a1,
                                     uint32_t a2, uint32_t a3,
                                     uint32_t b0, uint32_t b1) {
    asm volatile(
        "mma.sync.aligned.m16n8k8.row.col.f32.tf32.tf32.f32 "
        "{%0,%1,%2,%3},{%4,%5,%6,%7},{%8,%9},{%0,%1,%2,%3};"
        : "+f"(d[0]), "+f"(d[1]), "+f"(d[2]), "+f"(d[3])
        : "r"(a0), "r"(a1), "r"(a2), "r"(a3), "r"(b0), "r"(b1));
}
__device__ __forceinline__ void cp16(uint32_t dst, const float* src) {
    asm volatile("cp.async.cg.shared.global [%0], [%1], 16;" :: "r"(dst), "l"(src));
}
__device__ __forceinline__ void cp_commit() {
    asm volatile("cp.async.commit_group;" ::: "memory");
}
template<int N>
__device__ __forceinline__ void cp_wait() {
    asm volatile("cp.async.wait_group %0;" :: "n"(N) : "memory");
}

// ---------------- tf32 tensor-core GEMM: C[M,N] = A[M,K] @ B[N,K]^T ----------
// Operands pre-rounded tf32 + pre-packed. Block tile 256x128x32, 16 warps
// (4x4 warp grid, warp tile 64x32), cp.async 3-stage pipeline, 1 block/SM.
// MODE 0: plain
// MODE 1: causal decay + fused row-sum; blocks with n0 > m0+255 skipped; C packed
// MODE 2: per-row scale; K truncated to m0+256 (extra cols are exact zeros)
template<int MODE>
__global__ __launch_bounds__(512, 1)
void gemm_tc(const float* __restrict__ A, const float* __restrict__ Bm,
             float* __restrict__ C, int Kd, int N,
             long long sA, long long sB, long long sC,
             const float* __restrict__ p1, const float* __restrict__ p2,
             float* __restrict__ rsum, float scale)
{
    const int my = (MODE != 0) ? (gridDim.y - 1 - blockIdx.y) : blockIdx.y;
    const int m0 = my * 256, n0 = blockIdx.x * 128;
    if (MODE == 1 && n0 > m0 + 255) return;   // never read by PV

    extern __shared__ float smem[];   // A: [STAGES][2][256][16], B: [STAGES][2][128][16]
    const int bz = blockIdx.z;
    A  += (size_t)bz * sA;
    Bm += (size_t)bz * sB;
    C  += (size_t)bz * sC;
    const int tid = threadIdx.x, lane = tid & 31, warp = tid >> 5;
    const int wm = warp & 3, wn = warp >> 2;
    const int mbase = wm * 64, nbase = wn * 32;
    const int lr = lane >> 2, lc = lane & 3;
    const int zb = bz * S_LEN;
    const int Keff = (MODE == 2) ? (m0 + 256) : Kd;
    const int T = Keff >> 5;

    float acc[4][4][4];
#pragma unroll
    for (int i = 0; i < 4; i++)
#pragma unroll
        for (int j = 0; j < 4; j++)
#pragma unroll
            for (int r = 0; r < 4; r++) acc[i][j][r] = 0.f;

    // A staging: all 512 threads -> (row = tid>>1 of 256, half-chunk = tid&1)
    const int sr = tid >> 1, sch = tid & 1;
    const float* gA = A + (size_t)(m0 + sr) * Kd + sch * 16;
    const uint32_t sbase = (uint32_t)__cvta_generic_to_shared(smem);
    uint32_t dA[4];
    {
        int sw = ((sr >> 1) ^ (sch << 1)) & 3;
#pragma unroll
        for (int q = 0; q < 4; q++)
            dA[q] = sbase + (uint32_t)((sch * 4096 + sr * 16 + ((q ^ sw) * 4)) * 4);
    }
    // B staging: threads < 256 -> (row = tid>>1 of 128, half-chunk = tid&1)
    const bool doB = (tid < 256);
    const int srb = (tid >> 1) & 127, schb = tid & 1;
    const float* gB = Bm + (size_t)(n0 + srb) * Kd + schb * 16;
    uint32_t dB[4];
    {
        int sw = ((srb >> 1) ^ (schb << 1)) & 3;
#pragma unroll
        for (int q = 0; q < 4; q++)
            dB[q] = sbase + (uint32_t)(STAGES * 32768 +
                     (schb * 2048 + srb * 16 + ((q ^ sw) * 4)) * 4);
    }

    // prologue: stage 0 and 1
#pragma unroll
    for (int p = 0; p < 2; p++) {
        const float* pa = gA + p * 32;
        uint32_t soA = p * 32768;
#pragma unroll
        for (int q = 0; q < 4; q++) cp16(dA[q] + soA, pa + q * 4);
        if (doB) {
            const float* pb = gB + p * 32;
            uint32_t soB = p * 16384;
#pragma unroll
            for (int q = 0; q < 4; q++) cp16(dB[q] + soB, pb + q * 4);
        }
        cp_commit();
    }

    for (int t = 0; t < T; t++) {
        if (t + 1 < T) cp_wait<1>(); else cp_wait<0>();
        __syncthreads();
        if (t + 2 < T) {
            const int stg = (t + 2) % STAGES;
            const float* pa = gA + (t + 2) * 32;
            uint32_t soA = stg * 32768;
#pragma unroll
            for (int q = 0; q < 4; q++) cp16(dA[q] + soA, pa + q * 4);
            if (doB) {
                const float* pb = gB + (t + 2) * 32;
                uint32_t soB = stg * 16384;
#pragma unroll
                for (int q = 0; q < 4; q++) cp16(dB[q] + soB, pb + q * 4);
            }
            cp_commit();
        }
        const int stg = t % STAGES;
#pragma unroll
        for (int ch = 0; ch < 2; ch++) {
            const float* ba = smem + stg * 8192 + ch * 4096;
            const float* bb = smem + STAGES * 8192 + stg * 4096 + ch * 2048;
            uint4 af[4][2]; uint4 bf[4];
#pragma unroll
            for (int mt = 0; mt < 4; mt++) {
                int row = mbase + mt * 16 + lr;
                int pq = lc ^ (((row >> 1) ^ (ch << 1)) & 3);
                af[mt][0] = *(const uint4*)(ba + row * 16 + pq * 4);
                af[mt][1] = *(const uint4*)(ba + (row + 8) * 16 + pq * 4);
            }
#pragma unroll
            for (int nt = 0; nt < 4; nt++) {
                int nr = nbase + nt * 8 + lr;
                int pq = lc ^ (((nr >> 1) ^ (ch << 1)) & 3);
                bf[nt] = *(const uint4*)(bb + nr * 16 + pq * 4);
            }
#pragma unroll
            for (int mt = 0; mt < 4; mt++)
#pragma unroll
                for (int nt = 0; nt < 4; nt++) {
                    mma8(acc[mt][nt], af[mt][0].x, af[mt][1].x, af[mt][0].y, af[mt][1].y,
                         bf[nt].x, bf[nt].y);
                    mma8(acc[mt][nt], af[mt][0].z, af[mt][1].z, af[mt][0].w, af[mt][1].w,
                         bf[nt].z, bf[nt].w);
                }
        }
    }

    // epilogue
    float ac0[4], ac1[4];
    if (MODE == 1) {
#pragma unroll
        for (int nt = 0; nt < 4; nt++) {
            int c = n0 + nbase + nt * 8 + lc * 2;
            ac0[nt] = p1[zb + c];
            ac1[nt] = p1[zb + c + 1];
        }
    }
#pragma unroll
    for (int mt = 0; mt < 4; mt++) {
        int r1 = m0 + mbase + mt * 16 + lr;
        int r2 = r1 + 8;
        float am1 = 0.f, am2 = 0.f, s1 = 1.f, s2 = 1.f;
        if (MODE == 1) { am1 = p2[zb + r1]; am2 = p2[zb + r2]; }
        if (MODE == 2) { s1 = p1[zb + r1]; s2 = p1[zb + r2]; }
        float rowacc1 = 0.f, rowacc2 = 0.f;
#pragma unroll
        for (int nt = 0; nt < 4; nt++) {
            int c = n0 + nbase + nt * 8 + lc * 2;
            float* a4 = acc[mt][nt];
            float o0 = a4[0], o1 = a4[1], o2 = a4[2], o3 = a4[3];
            if (MODE == 1) {
                o0 *= (c     <= r1) ? scale * __expf(fminf(ac0[nt] - am1, 0.f)) : 0.f;
                o1 *= (c + 1 <= r1) ? scale * __expf(fminf(ac1[nt] - am1, 0.f)) : 0.f;
                o2 *= (c     <= r2) ? scale * __expf(fminf(ac0[nt] - am2, 0.f)) : 0.f;
                o3 *= (c + 1 <= r2) ? scale * __expf(fminf(ac1[nt] - am2, 0.f)) : 0.f;
                rowacc1 += o0 + o1;
                rowacc2 += o2 + o3;
                int p0 = ppos(c);
                C[(size_t)r1 * N + p0]     = f2tff(o0);
                C[(size_t)r1 * N + p0 + 4] = f2tff(o1);
                C[(size_t)r2 * N + p0]     = f2tff(o2);
                C[(size_t)r2 * N + p0 + 4] = f2tff(o3);
            } else {
                if (MODE == 2) { o0 *= s1; o1 *= s1; o2 *= s2; o3 *= s2; }
                *(float2*)(C + (size_t)r1 * N + c) = make_float2(o0, o1);
                *(float2*)(C + (size_t)r2 * N + c) = make_float2(o2, o3);
            }
        }
        if (MODE == 1) {
            atomicAdd(rsum + zb + r1, rowacc1);
            atomicAdd(rsum + zb + r2, rowacc2);
        }
    }
}

// ---------------- pack x to tf32 quad-interleaved ----------------
__global__ void pack_x_k(const float* __restrict__ in, float* __restrict__ out)
{
    int g = blockIdx.x * 256 + threadIdx.x;
    const float* p = in + (size_t)g * 16;
    float4 va[4];
#pragma unroll
    for (int i = 0; i < 4; i++) va[i] = *(const float4*)(p + 4 * i);
    const float* vf = (const float*)va;
    float* o = out + (size_t)g * 16;
#pragma unroll
    for (int q = 0; q < 4; q++) {
        float4 w = make_float4(f2tff(vf[q]), f2tff(vf[q + 4]),
                               f2tff(vf[q + 8]), f2tff(vf[q + 12]));
        *(float4*)(o + q * 4) = w;
    }
}

// ---------------- transpose + tf32 round + pack ----------------
__global__ void transpose_pk_k(const float* __restrict__ in, float* __restrict__ out,
                               int R, int Cc, long long sIn, long long sOut)
{
    __shared__ float tile[32][33];
    in  += (size_t)blockIdx.z * sIn;
    out += (size_t)blockIdx.z * sOut;
    int c0 = blockIdx.x * 32, r0 = blockIdx.y * 32;
    int x = threadIdx.x, y = threadIdx.y;
#pragma unroll
    for (int j = 0; j < 32; j += 8)
        tile[y + j][x] = in[(size_t)(r0 + y + j) * Cc + c0 + x];
    __syncthreads();
    int px = (x & 16) | ((x & 3) << 2) | ((x & 15) >> 2);
#pragma unroll
    for (int j = 0; j < 32; j += 8)
        out[(size_t)(c0 + y + j) * R + r0 + px] = f2tff(tile[x][y + j]);
}

// ---------------- causal depthwise conv (K=4) + swish ----------------
__global__ void conv_swish_k(const float* __restrict__ xinner,
                             const float* __restrict__ cw,
                             const float* __restrict__ cb,
                             float* __restrict__ xact)
{
    int idx = blockIdx.x * 256 + threadIdx.x;
    int c = idx & 2047;
    int r = idx >> 11;
    int s = r & 2047;
    const float* base = xinner + (size_t)r * 4096 + c;
    float acc = cb[c];
#pragma unroll
    for (int i = 0; i < 4; i++) {
        int sp = s - 3 + i;
        if (sp >= 0) acc = fmaf(base[(long long)(i - 3) * 4096], cw[i * 2048 + c], acc);
    }
    xact[idx] = acc / (1.f + __expf(-acc));
}

// ---------------- headwise q/k/v + gate preactivations ----------------
__global__ void qkv_gates_k(const float* __restrict__ xinner, const float* __restrict__ xact,
    const float* __restrict__ Wq, const float* __restrict__ Wk, const float* __restrict__ Wv,
    const float* __restrict__ Wig, const float* __restrict__ big,
    const float* __restrict__ Wfg, const float* __restrict__ bfg,
    float* __restrict__ q, float* __restrict__ k, float* __restrict__ v,
    float* __restrict__ ig, float* __restrict__ fgp)
{
    int r = blockIdx.x;
    int b = r >> 11, s = r & 2047;
    int tid = threadIdx.x;
    float igp[4] = {0, 0, 0, 0}, fgv[4] = {0, 0, 0, 0};
#pragma unroll
    for (int g = 0; g < 2; g++) {
        int c4 = tid * 8 + g * 4;
        int ph = c4 >> 2;
        float xa[4], xm[4];
#pragma unroll
        for (int d = 0; d < 4; d++) {
            xa[d] = xact[(size_t)r * 2048 + c4 + d];
            xm[d] = xinner[(size_t)r * 4096 + c4 + d];
        }
#pragma unroll
        for (int o = 0; o < 4; o++) {
            float qo = 0, ko = 0, vo = 0;
#pragma unroll
            for (int d = 0; d < 4; d++) {
                qo = fmaf(xa[d], Wq[ph * 16 + o * 4 + d], qo);
                ko = fmaf(xa[d], Wk[ph * 16 + o * 4 + d], ko);
                vo = fmaf(xm[d], Wv[ph * 16 + o * 4 + d], vo);
            }
            int c = c4 + o;
            int nh = c >> 9, dh = c & 511;
            size_t rowb = ((size_t)(b * 4 + nh) * 2048 + s) * 512;
            int pp = ppos(dh);
            q[rowb + pp] = f2tff(qo);
            k[rowb + pp] = f2tff(ko);
            v[rowb + dh] = vo;
#pragma unroll
            for (int n2 = 0; n2 < 4; n2++) {
                igp[n2] = fmaf(qo, Wig[c * 4 + n2], igp[n2]);
                igp[n2] = fmaf(ko, Wig[(2048 + c) * 4 + n2], igp[n2]);
                igp[n2] = fmaf(vo, Wig[(4096 + c) * 4 + n2], igp[n2]);
                fgv[n2] = fmaf(qo, Wfg[c * 4 + n2], fgv[n2]);
                fgv[n2] = fmaf(ko, Wfg[(2048 + c) * 4 + n2], fgv[n2]);
                fgv[n2] = fmaf(vo, Wfg[(4096 + c) * 4 + n2], fgv[n2]);
            }
        }
    }
#pragma unroll
    for (int off = 16; off; off >>= 1) {
#pragma unroll
        for (int n2 = 0; n2 < 4; n2++) {
            igp[n2] += __shfl_down_sync(0xffffffffu, igp[n2], off);
            fgv[n2] += __shfl_down_sync(0xffffffffu, fgv[n2], off);
        }
    }
    __shared__ float red[8][8];
    int wid = tid >> 5, lane = tid & 31;
    if (lane == 0) {
#pragma unroll
        for (int n2 = 0; n2 < 4; n2++) { red[wid][n2] = igp[n2]; red[wid][4 + n2] = fgv[n2]; }
    }
    __syncthreads();
    if (tid < 8) {
        float acc = 0.f;
        for (int w = 0; w < 8; w++) acc += red[w][tid];
        int n2 = tid & 3;
        if (tid < 4) ig [(size_t)(b * 4 + n2) * 2048 + s] = acc + big[n2];
        else         fgp[(size_t)(b * 4 + n2) * 2048 + s] = acc + bfg[n2];
    }
}

// ---------------- per-head scans ----------------
__global__ void scan_k(const float* __restrict__ ig, const float* __restrict__ fgp,
                       float* __restrict__ ga, float* __restrict__ gamax,
                       float* __restrict__ genm)
{
    const int bh = blockIdx.x, tid = threadIdx.x;
    const int base = bh * 2048;
    const int lane = tid & 31, warp = tid >> 5;
    float lf[8], aL[8], F[8];
    float s = 0.f;
#pragma unroll
    for (int j = 0; j < 8; j++) {
        float xv = fgp[base + tid * 8 + j];
        lf[j] = fminf(xv, 0.f) - log1pf(expf(-fabsf(xv)));
        s += lf[j];
    }
    __shared__ float wred[8];
    float inc = s;
#pragma unroll
    for (int off = 1; off < 32; off <<= 1) {
        float o = __shfl_up_sync(0xffffffffu, inc, off);
        if (lane >= off) inc += o;
    }
    float exc = __shfl_up_sync(0xffffffffu, inc, 1);
    if (lane == 0) exc = 0.f;
    if (lane == 31) wred[warp] = inc;
    __syncthreads();
    float wofs = 0.f;
#pragma unroll
    for (int w = 0; w < 8; w++) if (w < warp) wofs += wred[w];
    float run = wofs + exc;
#pragma unroll
    for (int j = 0; j < 8; j++) { run += lf[j]; F[j] = run; }
    __syncthreads();

    float mloc = -3.4e38f;
#pragma unroll
    for (int j = 0; j < 8; j++) {
        aL[j] = ig[base + tid * 8 + j] - F[j];
        mloc = fmaxf(mloc, aL[j]);
    }
    float minc = mloc;
#pragma unroll
    for (int off = 1; off < 32; off <<= 1) {
        float o = __shfl_up_sync(0xffffffffu, minc, off);
        if (lane >= off) minc = fmaxf(minc, o);
    }
    float mexc = __shfl_up_sync(0xffffffffu, minc, 1);
    if (lane == 0) mexc = -3.4e38f;
    if (lane == 31) wred[warp] = minc;
    __syncthreads();
    float wm = -3.4e38f;
#pragma unroll
    for (int w = 0; w < 8; w++) if (w < warp) wm = fmaxf(wm, wred[w]);
    float rm = fmaxf(wm, mexc);
#pragma unroll
    for (int j = 0; j < 8; j++) {
        rm = fmaxf(rm, aL[j]);
        int idx = base + tid * 8 + j;
        ga[idx] = aL[j];
        gamax[idx] = rm;
        genm[idx] = expf(-(F[j] + rm));
    }
}

// ---------------- finalize: inorm = 1/(max(|rowsum|, enm) + 1e-6) -----------
__global__ void finalize_norm_k(const float* __restrict__ rs, const float* __restrict__ enm,
                                float* __restrict__ inorm)
{
    int i = blockIdx.x * 256 + threadIdx.x;
    float nrm = fmaxf(fabsf(rs[i]), enm[i]);
    inorm[i] = 1.f / (nrm + 1e-6f);
}

// ---------------- per-(b,s,nh) layernorm + skip + swish(z); packed store ----
__global__ void ln_fuse_k(const float* __restrict__ h, const float* __restrict__ xact,
    const float* __restrict__ xinner, const float* __restrict__ nw,
    const float* __restrict__ sk, float* __restrict__ hstate)
{
    int r = blockIdx.x, nh = blockIdx.y, tid = threadIdx.x;
    int b = r >> 11, s = r & 2047;
    const float* hp = h + ((size_t)(b * 4 + nh) * 2048 + s) * 512;
    float4 hv = *(const float4*)(hp + tid * 4);
    float sum = hv.x + hv.y + hv.z + hv.w;
    for (int off = 16; off; off >>= 1) sum += __shfl_down_sync(0xffffffffu, sum, off);
    __shared__ float sred[4];
    __shared__ float smu, srstd;
    int wid = tid >> 5, lane = tid & 31;
    if (lane == 0) sred[wid] = sum;
    __syncthreads();
    if (tid == 0) smu = (sred[0] + sred[1] + sred[2] + sred[3]) * (1.f / 512.f);
    __syncthreads();
    float mu = smu;
    float dx = hv.x - mu, dy = hv.y - mu, dz = hv.z - mu, dw = hv.w - mu;
    float sq = dx * dx + dy * dy + dz * dz + dw * dw;
    for (int off = 16; off; off >>= 1) sq += __shfl_down_sync(0xffffffffu, sq, off);
    __syncthreads();
    if (lane == 0) sred[wid] = sq;
    __syncthreads();
    if (tid == 0) srstd = rsqrtf((sred[0] + sred[1] + sred[2] + sred[3]) * (1.f / 512.f) + 1e-6f);
    __syncthreads();
    float rstd = srstd;
    int c0 = nh * 512 + tid * 4;
    float4 nwv = *(const float4*)(nw + c0);
    float4 skv = *(const float4*)(sk + c0);
    float4 xav = *(const float4*)(xact + (size_t)r * 2048 + c0);
    float4 zv  = *(const float4*)(xinner + (size_t)r * 4096 + 2048 + c0);
    float o[4];
    o[0] = (dx * rstd * nwv.x + skv.x * xav.x) * (zv.x / (1.f + __expf(-zv.x)));
    o[1] = (dy * rstd * nwv.y + skv.y * xav.y) * (zv.y / (1.f + __expf(-zv.y)));
    o[2] = (dz * rstd * nwv.z + skv.z * xav.z) * (zv.z / (1.f + __expf(-zv.z)));
    o[3] = (dw * rstd * nwv.w + skv.w * xav.w) * (zv.w / (1.f + __expf(-zv.w)));
    float* hb = hstate + (size_t)r * 2048 + (c0 & ~15) + (tid & 3);
#pragma unroll
    for (int i = 0; i < 4; i++) hb[i << 2] = f2tff(o[i]);
}

// ---------------- launch ----------------
extern "C" void kernel_launch(void* const* d_in, const int* in_sizes, int n_in,
                              void* d_out, int out_size)
{
    (void)in_sizes; (void)n_in; (void)out_size;
    const float* x      = (const float*)d_in[0];
    const float* W_up   = (const float*)d_in[1];
    const float* conv_w = (const float*)d_in[2];
    const float* conv_b = (const float*)d_in[3];
    const float* Wq     = (const float*)d_in[4];
    const float* Wk     = (const float*)d_in[5];
    const float* Wv     = (const float*)d_in[6];
    const float* W_ig   = (const float*)d_in[7];
    const float* b_ig   = (const float*)d_in[8];
    const float* W_fg   = (const float*)d_in[9];
    const float* b_fg   = (const float*)d_in[10];
    const float* norm_w = (const float*)d_in[11];
    const float* skipw  = (const float*)d_in[12];
    const float* W_down = (const float*)d_in[13];
    float* out = (float*)d_out;

    float *xpk, *xinner, *xact, *q, *k, *v, *vT, *Cb, *h, *hstate, *WupT, *WdownT;
    float *ig, *fgp, *a, *amax, *enm, *inorm, *rowsum;
    cudaGetSymbolAddress((void**)&xpk,    g_xpk);
    cudaGetSymbolAddress((void**)&xinner, g_xinner);
    cudaGetSymbolAddress((void**)&xact,   g_xact);
    cudaGetSymbolAddress((void**)&q,      g_q);
    cudaGetSymbolAddress((void**)&k,      g_k);
    cudaGetSymbolAddress((void**)&v,      g_v);
    cudaGetSymbolAddress((void**)&vT,     g_vT);
    cudaGetSymbolAddress((void**)&Cb,     g_C);
    cudaGetSymbolAddress((void**)&h,      g_h);
    cudaGetSymbolAddress((void**)&hstate, g_hstate);
    cudaGetSymbolAddress((void**)&WupT,   g_WupT);
    cudaGetSymbolAddress((void**)&WdownT, g_WdownT);
    cudaGetSymbolAddress((void**)&ig,     g_ig);
    cudaGetSymbolAddress((void**)&fgp,    g_fgp);
    cudaGetSymbolAddress((void**)&a,      g_a);
    cudaGetSymbolAddress((void**)&amax,   g_amax);
    cudaGetSymbolAddress((void**)&enm,    g_enm);
    cudaGetSymbolAddress((void**)&inorm,  g_inorm);
    cudaGetSymbolAddress((void**)&rowsum, g_rowsum);

    const int SMEM = STAGES * (32768 + 16384);   // 144 KB
    cudaFuncSetAttribute((const void*)gemm_tc<0>, cudaFuncAttributeMaxDynamicSharedMemorySize, SMEM);
    cudaFuncSetAttribute((const void*)gemm_tc<1>, cudaFuncAttributeMaxDynamicSharedMemorySize, SMEM);
    cudaFuncSetAttribute((const void*)gemm_tc<2>, cudaFuncAttributeMaxDynamicSharedMemorySize, SMEM);

    const long long sQKV = (long long)S_LEN * DH_N;
    const long long sCC  = (long long)S_LEN * S_LEN;

    // 0) zero rowsum; pack x; transpose+round+pack weights
    cudaMemsetAsync(rowsum, 0, BH_N * S_LEN * sizeof(float));
    pack_x_k<<<(M_ROWS * E_DIM / 16) / 256, 256>>>(x, xpk);
    transpose_pk_k<<<dim3(128, 32, 1), dim3(32, 8)>>>(W_up,   WupT,   1024, 4096, 0, 0);
    transpose_pk_k<<<dim3(32,  64, 1), dim3(32, 8)>>>(W_down, WdownT, 2048, 1024, 0, 0);

    // 1) up projection (M-blocks of 256)
    gemm_tc<0><<<dim3(32, 16, 1), 512, SMEM>>>(xpk, WupT, xinner, 1024, 4096,
                                               0, 0, 0, nullptr, nullptr, nullptr, 0.f);
    // 2) causal conv + swish
    conv_swish_k<<<32768, 256>>>(xinner, conv_w, conv_b, xact);
    // 3) headwise q/k/v + gate preactivations
    qkv_gates_k<<<4096, 256>>>(xinner, xact, Wq, Wk, Wv, W_ig, b_ig, W_fg, b_fg,
                               q, k, v, ig, fgp);
    // 3b) transpose+round+pack V per head
    transpose_pk_k<<<dim3(16, 64, 8), dim3(32, 8)>>>(v, vT, 2048, 512, sQKV, sQKV);
    // 4) per-head scans
    scan_k<<<8, 256>>>(ig, fgp, a, amax, enm);
    // 5) weighted causal scores + fused row sums
    gemm_tc<1><<<dim3(16, 8, 8), 512, SMEM>>>(q, k, Cb, 512, 2048,
                                              sQKV, sQKV, sCC, a, amax, rowsum,
                                              0.044194173824159216f);
    // 6) finalize norms
    finalize_norm_k<<<64, 256>>>(rowsum, enm, inorm);
    // 7) h = diag(inorm) C @ V  (K truncated to m0+256)
    gemm_tc<2><<<dim3(4, 8, 8), 512, SMEM>>>(Cb, vT, h, 2048, 512,
                                             sCC, sQKV, sQKV, inorm, nullptr, nullptr, 0.f);
    // 8) multihead LN + skip + swish(z) gate
    ln_fuse_k<<<dim3(4096, 4), 128>>>(h, xact, xinner, norm_w, skipw, hstate);
    // 9) down projection -> output
    gemm_tc<0><<<dim3(8, 16, 1), 512, SMEM>>>(hstate, WdownT, out, 2048, 1024,
                                              0, 0, 0, nullptr, nullptr, nullptr, 0.f);
}

// round 9
// speedup vs baseline: 1.4035x; 1.3879x over previous
#include <cuda_runtime.h>
#include <cuda_fp16.h>
#include <math.h>
#include <stdint.h>

// Problem constants
#define S_LEN   2048
#define E_DIM   1024
#define INNER_D 2048
#define NH_N    4
#define DH_N    512
#define M_ROWS  4096   // B*S
#define BH_N    8      // B*NH
#define STAGES  3

// ---------------- scratch (device globals; no allocs allowed) ----------------
__device__ __half g_xpk   [(size_t)M_ROWS * E_DIM];      // packed fp16 x
__device__ float  g_xinner[(size_t)M_ROWS * 4096];
__device__ float  g_xact  [(size_t)M_ROWS * INNER_D];
__device__ __half g_q     [(size_t)BH_N * S_LEN * DH_N]; // packed fp16
__device__ __half g_k     [(size_t)BH_N * S_LEN * DH_N]; // packed fp16
__device__ float  g_v     [(size_t)BH_N * S_LEN * DH_N]; // plain
__device__ __half g_vT    [(size_t)BH_N * S_LEN * DH_N]; // packed fp16
__device__ __half g_C     [(size_t)BH_N * S_LEN * S_LEN];// packed fp16 (upper tri stays 0)
__device__ float  g_h     [(size_t)BH_N * S_LEN * DH_N]; // plain
__device__ __half g_hstate[(size_t)M_ROWS * INNER_D];    // packed fp16
__device__ __half g_WupT  [(size_t)4096 * 1024];         // packed fp16
__device__ __half g_WdownT[(size_t)1024 * 2048];         // packed fp16
__device__ float  g_ig    [BH_N * S_LEN];
__device__ float  g_fgp   [BH_N * S_LEN];
__device__ float  g_a     [BH_N * S_LEN];
__device__ float  g_amax  [BH_N * S_LEN];
__device__ float  g_enm   [BH_N * S_LEN];
__device__ float  g_inorm [BH_N * S_LEN];
__device__ float  g_rowsum[BH_N * S_LEN];

// ---------------- helpers ----------------
// packed half index within a row for element k (32-k groups, pair-interleaved,
// per-row group rotation): granule g holds pairs (p_g, p_{g+4}) of both 16-k chunks.
__device__ __forceinline__ int ppk(int r, int k) {
    int c = (k >> 4) & 1, kk = k & 15, p = kk >> 1;
    int g = ((p & 3) + ((r >> 1) & 3)) & 3;
    return (k & ~31) + g * 8 + (p >> 2) * 4 + c * 2 + (kk & 1);
}

__device__ __forceinline__ void mma16(float* d, uint32_t a0, uint32_t a1,
                                      uint32_t a2, uint32_t a3,
                                      uint32_t b0, uint32_t b1) {
    asm volatile(
        "mma.sync.aligned.m16n8k16.row.col.f32.f16.f16.f32 "
        "{%0,%1,%2,%3},{%4,%5,%6,%7},{%8,%9},{%0,%1,%2,%3};"
        : "+f"(d[0]), "+f"(d[1]), "+f"(d[2]), "+f"(d[3])
        : "r"(a0), "r"(a1), "r"(a2), "r"(a3), "r"(b0), "r"(b1));
}
__device__ __forceinline__ void cp16(uint32_t dst, const void* src) {
    asm volatile("cp.async.cg.shared.global [%0], [%1], 16;" :: "r"(dst), "l"(src));
}
__device__ __forceinline__ void cp_commit() {
    asm volatile("cp.async.commit_group;" ::: "memory");
}
template<int N>
__device__ __forceinline__ void cp_wait() {
    asm volatile("cp.async.wait_group %0;" :: "n"(N) : "memory");
}

// ---------------- fp16 tensor-core GEMM: C[M,N] = A[M,K] @ B[N,K]^T ---------
// Operands pre-rounded fp16 + pre-packed/swizzled. Block tile 256x128x32,
// 16 warps (4x4 warp grid, warp tile 64x32), cp.async 3-stage, 1 block/SM.
// MODE 0: plain (float out)
// MODE 1: causal decay + fused row-sum; blocks n0 > m0+255 skipped; C fp16 packed
// MODE 2: per-row scale; K truncated to m0+256 (extra cols exact zeros); float out
template<int MODE>
__global__ __launch_bounds__(512, 1)
void gemm_tc(const __half* __restrict__ A, const __half* __restrict__ Bm,
             void* __restrict__ Cv, int Kd, int N,
             long long sA, long long sB, long long sC,
             const float* __restrict__ p1, const float* __restrict__ p2,
             float* __restrict__ rsum, float scale)
{
    const int my = (MODE != 0) ? (gridDim.y - 1 - blockIdx.y) : blockIdx.y;
    const int m0 = my * 256, n0 = blockIdx.x * 128;
    if (MODE == 1 && n0 > m0 + 255) return;   // never read by PV

    extern __shared__ char smemc[];   // A: [STAGES][256*64B], B: [STAGES][128*64B]
    const int bz = blockIdx.z;
    A  += (size_t)bz * sA;
    Bm += (size_t)bz * sB;
    const int tid = threadIdx.x, lane = tid & 31, warp = tid >> 5;
    const int wm = warp & 3, wn = warp >> 2;
    const int mbase = wm * 64, nbase = wn * 32;
    const int lr = lane >> 2, t4 = lane & 3;
    const int zb = bz * S_LEN;
    const int Keff = (MODE == 2) ? (m0 + 256) : Kd;
    const int T = Keff >> 5;

    float acc[4][4][4];
#pragma unroll
    for (int i = 0; i < 4; i++)
#pragma unroll
        for (int j = 0; j < 4; j++)
#pragma unroll
            for (int r = 0; r < 4; r++) acc[i][j][r] = 0.f;

    // staging: thread t -> A rows (t>>2) and (t>>2)+128, granule t&3; B row t>>2
    const int arow = tid >> 2, agr = tid & 3;
    const __half* gA0 = A  + (size_t)(m0 + arow) * Kd + agr * 8;
    const __half* gA1 = A  + (size_t)(m0 + arow + 128) * Kd + agr * 8;
    const __half* gB0 = Bm + (size_t)(n0 + arow) * Kd + agr * 8;
    const uint32_t sbase = (uint32_t)__cvta_generic_to_shared(smemc);
    const uint32_t dA0 = sbase + arow * 64 + agr * 16;
    const uint32_t dA1 = sbase + (arow + 128) * 64 + agr * 16;
    const uint32_t dB  = sbase + STAGES * 16384 + arow * 64 + agr * 16;

    // prologue: stage 0 and 1
#pragma unroll
    for (int p = 0; p < 2; p++) {
        cp16(dA0 + p * 16384, gA0 + p * 32);
        cp16(dA1 + p * 16384, gA1 + p * 32);
        cp16(dB  + p * 8192,  gB0 + p * 32);
        cp_commit();
    }

    for (int t = 0; t < T; t++) {
        if (t + 1 < T) cp_wait<1>(); else cp_wait<0>();
        __syncthreads();
        if (t + 2 < T) {
            const int stg = (t + 2) % STAGES;
            cp16(dA0 + stg * 16384, gA0 + (t + 2) * 32);
            cp16(dA1 + stg * 16384, gA1 + (t + 2) * 32);
            cp16(dB  + stg * 8192,  gB0 + (t + 2) * 32);
            cp_commit();
        }
        const int stg = t % STAGES;
        const char* baseA = smemc + stg * 16384;
        const char* baseB = smemc + STAGES * 16384 + stg * 8192;
        uint4 af0[4], af1[4], bf[4];
#pragma unroll
        for (int mt = 0; mt < 4; mt++) {
            int r = mbase + mt * 16 + lr;
            int go = 16 * ((t4 + ((r >> 1) & 3)) & 3);
            af0[mt] = *(const uint4*)(baseA + r * 64 + go);
            af1[mt] = *(const uint4*)(baseA + (r + 8) * 64 + go);
        }
#pragma unroll
        for (int nt = 0; nt < 4; nt++) {
            int rb = nbase + nt * 8 + lr;
            int go = 16 * ((t4 + ((rb >> 1) & 3)) & 3);
            bf[nt] = *(const uint4*)(baseB + rb * 64 + go);
        }
#pragma unroll
        for (int mt = 0; mt < 4; mt++)
#pragma unroll
            for (int nt = 0; nt < 4; nt++) {
                // chunk 0 (k 0..15): components .x (pair t), .z (pair t+4)
                mma16(acc[mt][nt], af0[mt].x, af1[mt].x, af0[mt].z, af1[mt].z,
                      bf[nt].x, bf[nt].z);
                // chunk 1 (k 16..31): components .y, .w
                mma16(acc[mt][nt], af0[mt].y, af1[mt].y, af0[mt].w, af1[mt].w,
                      bf[nt].y, bf[nt].w);
            }
    }

    // epilogue
    __half* Ch = (MODE == 1) ? ((__half*)Cv + (size_t)bz * sC) : nullptr;
    float*  Cf = (MODE != 1) ? ((float*)Cv + (size_t)bz * sC) : nullptr;
    float ac0[4], ac1[4];
    if (MODE == 1) {
#pragma unroll
        for (int nt = 0; nt < 4; nt++) {
            int c = n0 + nbase + nt * 8 + t4 * 2;
            ac0[nt] = p1[zb + c];
            ac1[nt] = p1[zb + c + 1];
        }
    }
#pragma unroll
    for (int mt = 0; mt < 4; mt++) {
        int r1 = m0 + mbase + mt * 16 + lr;
        int r2 = r1 + 8;
        float am1 = 0.f, am2 = 0.f, s1 = 1.f, s2 = 1.f;
        if (MODE == 1) { am1 = p2[zb + r1]; am2 = p2[zb + r2]; }
        if (MODE == 2) { s1 = p1[zb + r1]; s2 = p1[zb + r2]; }
        float rowacc1 = 0.f, rowacc2 = 0.f;
#pragma unroll
        for (int nt = 0; nt < 4; nt++) {
            int c = n0 + nbase + nt * 8 + t4 * 2;
            float* a4 = acc[mt][nt];
            float o0 = a4[0], o1 = a4[1], o2 = a4[2], o3 = a4[3];
            if (MODE == 1) {
                o0 *= (c     <= r1) ? scale * __expf(fminf(ac0[nt] - am1, 0.f)) : 0.f;
                o1 *= (c + 1 <= r1) ? scale * __expf(fminf(ac1[nt] - am1, 0.f)) : 0.f;
                o2 *= (c     <= r2) ? scale * __expf(fminf(ac0[nt] - am2, 0.f)) : 0.f;
                o3 *= (c + 1 <= r2) ? scale * __expf(fminf(ac1[nt] - am2, 0.f)) : 0.f;
                rowacc1 += o0 + o1;
                rowacc2 += o2 + o3;
                *(__half2*)(Ch + (size_t)r1 * N + ppk(r1, c)) = __floats2half2_rn(o0, o1);
                *(__half2*)(Ch + (size_t)r2 * N + ppk(r2, c)) = __floats2half2_rn(o2, o3);
            } else {
                if (MODE == 2) { o0 *= s1; o1 *= s1; o2 *= s2; o3 *= s2; }
                *(float2*)(Cf + (size_t)r1 * N + c) = make_float2(o0, o1);
                *(float2*)(Cf + (size_t)r2 * N + c) = make_float2(o2, o3);
            }
        }
        if (MODE == 1) {
            atomicAdd(rsum + zb + r1, rowacc1);
            atomicAdd(rsum + zb + r2, rowacc2);
        }
    }
}

// ---------------- pack x to fp16 packed (one thread per 32-k group) ---------
__global__ void pack_x_k(const float* __restrict__ in, __half* __restrict__ out)
{
    int g = blockIdx.x * 256 + threadIdx.x;       // 32-float group index
    int r = g >> 5;                                // row (E=1024 -> 32 groups/row)
    const float* p = in + (size_t)g * 32;
    float buf[32];
#pragma unroll
    for (int i = 0; i < 8; i++) *(float4*)(buf + 4 * i) = *(const float4*)(p + 4 * i);
    __half hb[32];
#pragma unroll
    for (int j = 0; j < 32; j++) hb[ppk(r, j)] = __float2half_rn(buf[j]);
    uint4* o = (uint4*)(out + (size_t)g * 32);
#pragma unroll
    for (int i = 0; i < 4; i++) o[i] = ((uint4*)hb)[i];
}

// ---------------- transpose + fp16 round + pack: out[Cc][R] packed ----------
__global__ void transpose_pk_k(const float* __restrict__ in, __half* __restrict__ out,
                               int R, int Cc, long long sIn, long long sOut)
{
    __shared__ float tile[32][33];
    in  += (size_t)blockIdx.z * sIn;
    out += (size_t)blockIdx.z * sOut;
    int c0 = blockIdx.x * 32, r0 = blockIdx.y * 32;
    int x = threadIdx.x, y = threadIdx.y;   // 32 x 8
#pragma unroll
    for (int j = 0; j < 32; j += 8)
        tile[y + j][x] = in[(size_t)(r0 + y + j) * Cc + c0 + x];
    __syncthreads();
#pragma unroll
    for (int j = 0; j < 32; j += 8) {
        int orow = c0 + y + j;
        out[(size_t)orow * R + r0 + ppk(orow, x)] = __float2half_rn(tile[x][y + j]);
    }
}

// ---------------- causal depthwise conv (K=4) + swish ----------------
__global__ void conv_swish_k(const float* __restrict__ xinner,
                             const float* __restrict__ cw,
                             const float* __restrict__ cb,
                             float* __restrict__ xact)
{
    int idx = blockIdx.x * 256 + threadIdx.x;
    int c = idx & 2047;
    int r = idx >> 11;
    int s = r & 2047;
    const float* base = xinner + (size_t)r * 4096 + c;
    float acc = cb[c];
#pragma unroll
    for (int i = 0; i < 4; i++) {
        int sp = s - 3 + i;
        if (sp >= 0) acc = fmaf(base[(long long)(i - 3) * 4096], cw[i * 2048 + c], acc);
    }
    xact[idx] = acc / (1.f + __expf(-acc));
}

// ---------------- headwise q/k/v + gate preactivations ----------------
__global__ void qkv_gates_k(const float* __restrict__ xinner, const float* __restrict__ xact,
    const float* __restrict__ Wq, const float* __restrict__ Wk, const float* __restrict__ Wv,
    const float* __restrict__ Wig, const float* __restrict__ big,
    const float* __restrict__ Wfg, const float* __restrict__ bfg,
    __half* __restrict__ q, __half* __restrict__ k, float* __restrict__ v,
    float* __restrict__ ig, float* __restrict__ fgp)
{
    int r = blockIdx.x;
    int b = r >> 11, s = r & 2047;
    int tid = threadIdx.x;
    float igp[4] = {0, 0, 0, 0}, fgv[4] = {0, 0, 0, 0};
#pragma unroll
    for (int g = 0; g < 2; g++) {
        int c4 = tid * 8 + g * 4;
        int ph = c4 >> 2;
        float xa[4], xm[4], qv[4], kv[4];
#pragma unroll
        for (int d = 0; d < 4; d++) {
            xa[d] = xact[(size_t)r * 2048 + c4 + d];
            xm[d] = xinner[(size_t)r * 4096 + c4 + d];
        }
        int nh = c4 >> 9, dh0 = c4 & 511;
        size_t rowb = ((size_t)(b * 4 + nh) * 2048 + s) * 512;
#pragma unroll
        for (int o = 0; o < 4; o++) {
            float qo = 0, ko = 0, vo = 0;
#pragma unroll
            for (int d = 0; d < 4; d++) {
                qo = fmaf(xa[d], Wq[ph * 16 + o * 4 + d], qo);
                ko = fmaf(xa[d], Wk[ph * 16 + o * 4 + d], ko);
                vo = fmaf(xm[d], Wv[ph * 16 + o * 4 + d], vo);
            }
            qv[o] = qo; kv[o] = ko;
            int c = c4 + o;
            v[rowb + dh0 + o] = vo;
#pragma unroll
            for (int n2 = 0; n2 < 4; n2++) {
                igp[n2] = fmaf(qo, Wig[c * 4 + n2], igp[n2]);
                igp[n2] = fmaf(ko, Wig[(2048 + c) * 4 + n2], igp[n2]);
                igp[n2] = fmaf(vo, Wig[(4096 + c) * 4 + n2], igp[n2]);
                fgv[n2] = fmaf(qo, Wfg[c * 4 + n2], fgv[n2]);
                fgv[n2] = fmaf(ko, Wfg[(2048 + c) * 4 + n2], fgv[n2]);
                fgv[n2] = fmaf(vo, Wfg[(4096 + c) * 4 + n2], fgv[n2]);
            }
        }
        // packed fp16 stores (pairs share the same k-pair slot)
        *(__half2*)(q + rowb + ppk(s, dh0))     = __floats2half2_rn(qv[0], qv[1]);
        *(__half2*)(q + rowb + ppk(s, dh0 + 2)) = __floats2half2_rn(qv[2], qv[3]);
        *(__half2*)(k + rowb + ppk(s, dh0))     = __floats2half2_rn(kv[0], kv[1]);
        *(__half2*)(k + rowb + ppk(s, dh0 + 2)) = __floats2half2_rn(kv[2], kv[3]);
    }
#pragma unroll
    for (int off = 16; off; off >>= 1) {
#pragma unroll
        for (int n2 = 0; n2 < 4; n2++) {
            igp[n2] += __shfl_down_sync(0xffffffffu, igp[n2], off);
            fgv[n2] += __shfl_down_sync(0xffffffffu, fgv[n2], off);
        }
    }
    __shared__ float red[8][8];
    int wid = tid >> 5, lane = tid & 31;
    if (lane == 0) {
#pragma unroll
        for (int n2 = 0; n2 < 4; n2++) { red[wid][n2] = igp[n2]; red[wid][4 + n2] = fgv[n2]; }
    }
    __syncthreads();
    if (tid < 8) {
        float acc = 0.f;
        for (int w = 0; w < 8; w++) acc += red[w][tid];
        int n2 = tid & 3;
        if (tid < 4) ig [(size_t)(b * 4 + n2) * 2048 + s] = acc + big[n2];
        else         fgp[(size_t)(b * 4 + n2) * 2048 + s] = acc + bfg[n2];
    }
}

// ---------------- per-head scans ----------------
__global__ void scan_k(const float* __restrict__ ig, const float* __restrict__ fgp,
                       float* __restrict__ ga, float* __restrict__ gamax,
                       float* __restrict__ genm)
{
    const int bh = blockIdx.x, tid = threadIdx.x;
    const int base = bh * 2048;
    const int lane = tid & 31, warp = tid >> 5;
    float lf[8], aL[8], F[8];
    float s = 0.f;
#pragma unroll
    for (int j = 0; j < 8; j++) {
        float xv = fgp[base + tid * 8 + j];
        lf[j] = fminf(xv, 0.f) - log1pf(expf(-fabsf(xv)));
        s += lf[j];
    }
    __shared__ float wred[8];
    float inc = s;
#pragma unroll
    for (int off = 1; off < 32; off <<= 1) {
        float o = __shfl_up_sync(0xffffffffu, inc, off);
        if (lane >= off) inc += o;
    }
    float exc = __shfl_up_sync(0xffffffffu, inc, 1);
    if (lane == 0) exc = 0.f;
    if (lane == 31) wred[warp] = inc;
    __syncthreads();
    float wofs = 0.f;
#pragma unroll
    for (int w = 0; w < 8; w++) if (w < warp) wofs += wred[w];
    float run = wofs + exc;
#pragma unroll
    for (int j = 0; j < 8; j++) { run += lf[j]; F[j] = run; }
    __syncthreads();

    float mloc = -3.4e38f;
#pragma unroll
    for (int j = 0; j < 8; j++) {
        aL[j] = ig[base + tid * 8 + j] - F[j];
        mloc = fmaxf(mloc, aL[j]);
    }
    float minc = mloc;
#pragma unroll
    for (int off = 1; off < 32; off <<= 1) {
        float o = __shfl_up_sync(0xffffffffu, minc, off);
        if (lane >= off) minc = fmaxf(minc, o);
    }
    float mexc = __shfl_up_sync(0xffffffffu, minc, 1);
    if (lane == 0) mexc = -3.4e38f;
    if (lane == 31) wred[warp] = minc;
    __syncthreads();
    float wm = -3.4e38f;
#pragma unroll
    for (int w = 0; w < 8; w++) if (w < warp) wm = fmaxf(wm, wred[w]);
    float rm = fmaxf(wm, mexc);
#pragma unroll
    for (int j = 0; j < 8; j++) {
        rm = fmaxf(rm, aL[j]);
        int idx = base + tid * 8 + j;
        ga[idx] = aL[j];
        gamax[idx] = rm;
        genm[idx] = expf(-(F[j] + rm));
    }
}

// ---------------- finalize: inorm = 1/(max(|rowsum|, enm) + 1e-6) -----------
__global__ void finalize_norm_k(const float* __restrict__ rs, const float* __restrict__ enm,
                                float* __restrict__ inorm)
{
    int i = blockIdx.x * 256 + threadIdx.x;
    float nrm = fmaxf(fabsf(rs[i]), enm[i]);
    inorm[i] = 1.f / (nrm + 1e-6f);
}

// ---------------- per-(b,s,nh) layernorm + skip + swish(z); packed store ----
__global__ void ln_fuse_k(const float* __restrict__ h, const float* __restrict__ xact,
    const float* __restrict__ xinner, const float* __restrict__ nw,
    const float* __restrict__ sk, __half* __restrict__ hstate)
{
    int r = blockIdx.x, nh = blockIdx.y, tid = threadIdx.x;
    int b = r >> 11, s = r & 2047;
    const float* hp = h + ((size_t)(b * 4 + nh) * 2048 + s) * 512;
    float4 hv = *(const float4*)(hp + tid * 4);
    float sum = hv.x + hv.y + hv.z + hv.w;
    for (int off = 16; off; off >>= 1) sum += __shfl_down_sync(0xffffffffu, sum, off);
    __shared__ float sred[4];
    __shared__ float smu, srstd;
    int wid = tid >> 5, lane = tid & 31;
    if (lane == 0) sred[wid] = sum;
    __syncthreads();
    if (tid == 0) smu = (sred[0] + sred[1] + sred[2] + sred[3]) * (1.f / 512.f);
    __syncthreads();
    float mu = smu;
    float dx = hv.x - mu, dy = hv.y - mu, dz = hv.z - mu, dw = hv.w - mu;
    float sq = dx * dx + dy * dy + dz * dz + dw * dw;
    for (int off = 16; off; off >>= 1) sq += __shfl_down_sync(0xffffffffu, sq, off);
    __syncthreads();
    if (lane == 0) sred[wid] = sq;
    __syncthreads();
    if (tid == 0) srstd = rsqrtf((sred[0] + sred[1] + sred[2] + sred[3]) * (1.f / 512.f) + 1e-6f);
    __syncthreads();
    float rstd = srstd;
    int c0 = nh * 512 + tid * 4;
    float4 nwv = *(const float4*)(nw + c0);
    float4 skv = *(const float4*)(sk + c0);
    float4 xav = *(const float4*)(xact + (size_t)r * 2048 + c0);
    float4 zv  = *(const float4*)(xinner + (size_t)r * 4096 + 2048 + c0);
    float o[4];
    o[0] = (dx * rstd * nwv.x + skv.x * xav.x) * (zv.x / (1.f + __expf(-zv.x)));
    o[1] = (dy * rstd * nwv.y + skv.y * xav.y) * (zv.y / (1.f + __expf(-zv.y)));
    o[2] = (dz * rstd * nwv.z + skv.z * xav.z) * (zv.z / (1.f + __expf(-zv.z)));
    o[3] = (dw * rstd * nwv.w + skv.w * xav.w) * (zv.w / (1.f + __expf(-zv.w)));
    __half* hb = hstate + (size_t)r * 2048;
    *(__half2*)(hb + ppk(r, c0))     = __floats2half2_rn(o[0], o[1]);
    *(__half2*)(hb + ppk(r, c0 + 2)) = __floats2half2_rn(o[2], o[3]);
}

// ---------------- launch ----------------
extern "C" void kernel_launch(void* const* d_in, const int* in_sizes, int n_in,
                              void* d_out, int out_size)
{
    (void)in_sizes; (void)n_in; (void)out_size;
    const float* x      = (const float*)d_in[0];
    const float* W_up   = (const float*)d_in[1];
    const float* conv_w = (const float*)d_in[2];
    const float* conv_b = (const float*)d_in[3];
    const float* Wq     = (const float*)d_in[4];
    const float* Wk     = (const float*)d_in[5];
    const float* Wv     = (const float*)d_in[6];
    const float* W_ig   = (const float*)d_in[7];
    const float* b_ig   = (const float*)d_in[8];
    const float* W_fg   = (const float*)d_in[9];
    const float* b_fg   = (const float*)d_in[10];
    const float* norm_w = (const float*)d_in[11];
    const float* skipw  = (const float*)d_in[12];
    const float* W_down = (const float*)d_in[13];
    float* out = (float*)d_out;

    __half *xpk, *q, *k, *vT, *Cb, *hstate, *WupT, *WdownT;
    float *xinner, *xact, *v, *h;
    float *ig, *fgp, *a, *amax, *enm, *inorm, *rowsum;
    cudaGetSymbolAddress((void**)&xpk,    g_xpk);
    cudaGetSymbolAddress((void**)&xinner, g_xinner);
    cudaGetSymbolAddress((void**)&xact,   g_xact);
    cudaGetSymbolAddress((void**)&q,      g_q);
    cudaGetSymbolAddress((void**)&k,      g_k);
    cudaGetSymbolAddress((void**)&v,      g_v);
    cudaGetSymbolAddress((void**)&vT,     g_vT);
    cudaGetSymbolAddress((void**)&Cb,     g_C);
    cudaGetSymbolAddress((void**)&h,      g_h);
    cudaGetSymbolAddress((void**)&hstate, g_hstate);
    cudaGetSymbolAddress((void**)&WupT,   g_WupT);
    cudaGetSymbolAddress((void**)&WdownT, g_WdownT);
    cudaGetSymbolAddress((void**)&ig,     g_ig);
    cudaGetSymbolAddress((void**)&fgp,    g_fgp);
    cudaGetSymbolAddress((void**)&a,      g_a);
    cudaGetSymbolAddress((void**)&amax,   g_amax);
    cudaGetSymbolAddress((void**)&enm,    g_enm);
    cudaGetSymbolAddress((void**)&inorm,  g_inorm);
    cudaGetSymbolAddress((void**)&rowsum, g_rowsum);

    const int SMEM = STAGES * (16384 + 8192);   // 72 KB
    cudaFuncSetAttribute((const void*)gemm_tc<0>, cudaFuncAttributeMaxDynamicSharedMemorySize, SMEM);
    cudaFuncSetAttribute((const void*)gemm_tc<1>, cudaFuncAttributeMaxDynamicSharedMemorySize, SMEM);
    cudaFuncSetAttribute((const void*)gemm_tc<2>, cudaFuncAttributeMaxDynamicSharedMemorySize, SMEM);

    const long long sQKV = (long long)S_LEN * DH_N;
    const long long sCC  = (long long)S_LEN * S_LEN;

    // 0) zero rowsum; pack x; transpose+round+pack weights
    cudaMemsetAsync(rowsum, 0, BH_N * S_LEN * sizeof(float));
    pack_x_k<<<(M_ROWS * E_DIM / 32) / 256, 256>>>(x, xpk);
    transpose_pk_k<<<dim3(128, 32, 1), dim3(32, 8)>>>(W_up,   WupT,   1024, 4096, 0, 0);
    transpose_pk_k<<<dim3(32,  64, 1), dim3(32, 8)>>>(W_down, WdownT, 2048, 1024, 0, 0);

    // 1) up projection (M-blocks of 256)
    gemm_tc<0><<<dim3(32, 16, 1), 512, SMEM>>>(xpk, WupT, xinner, 1024, 4096,
                                               0, 0, 0, nullptr, nullptr, nullptr, 0.f);
    // 2) causal conv + swish
    conv_swish_k<<<32768, 256>>>(xinner, conv_w, conv_b, xact);
    // 3) headwise q/k/v + gate preactivations (q,k fp16 packed)
    qkv_gates_k<<<4096, 256>>>(xinner, xact, Wq, Wk, Wv, W_ig, b_ig, W_fg, b_fg,
                               q, k, v, ig, fgp);
    // 3b) transpose+round+pack V per head: vT[bh][dh][s]
    transpose_pk_k<<<dim3(16, 64, 8), dim3(32, 8)>>>(v, vT, 2048, 512, sQKV, sQKV);
    // 4) per-head scans
    scan_k<<<8, 256>>>(ig, fgp, a, amax, enm);
    // 5) weighted causal scores + fused row sums (C fp16 packed)
    gemm_tc<1><<<dim3(16, 8, 8), 512, SMEM>>>(q, k, Cb, 512, 2048,
                                              sQKV, sQKV, sCC, a, amax, rowsum,
                                              0.044194173824159216f);
    // 6) finalize norms
    finalize_norm_k<<<64, 256>>>(rowsum, enm, inorm);
    // 7) h = diag(inorm) C @ V  (K truncated to m0+256)
    gemm_tc<2><<<dim3(4, 8, 8), 512, SMEM>>>(Cb, vT, h, 2048, 512,
                                             sCC, sQKV, sQKV, inorm, nullptr, nullptr, 0.f);
    // 8) multihead LN + skip + swish(z) gate (hstate fp16 packed)
    ln_fuse_k<<<dim3(4096, 4), 128>>>(h, xact, xinner, norm_w, skipw, hstate);
    // 9) down projection -> output
    gemm_tc<0><<<dim3(8, 16, 1), 512, SMEM>>>(hstate, WdownT, out, 2048, 1024,
                                              0, 0, 0, nullptr, nullptr, nullptr, 0.f);
}